// round 9
// baseline (speedup 1.0000x reference)
#include <cuda_runtime.h>
#include <cuda_fp16.h>
#include <math.h>

#define B_   128
#define NJ   10
#define NK   1152
#define NM   16
#define NI   8
#define UHR  84          // route smem row pitch in half2 (80 data + 4 pad, 16B-aligned)

typedef unsigned long long ull;

// ---- f32x2 packed helpers (sm_100+) ----
__device__ __forceinline__ ull pk2(float lo, float hi) {
    ull r; asm("mov.b64 %0,{%1,%2};" : "=l"(r) : "f"(lo), "f"(hi)); return r;
}
__device__ __forceinline__ void upk2(ull v, float& lo, float& hi) {
    asm("mov.b64 {%0,%1},%2;" : "=f"(lo), "=f"(hi) : "l"(v));
}
__device__ __forceinline__ ull mul2(ull a, ull b) {
    ull d; asm("mul.rn.f32x2 %0,%1,%2;" : "=l"(d) : "l"(a), "l"(b)); return d;
}
__device__ __forceinline__ ull fma2(ull a, ull b, ull c) {
    ull d; asm("fma.rn.f32x2 %0,%1,%2,%3;" : "=l"(d) : "l"(a), "l"(b), "l"(c)); return d;
}
__device__ __forceinline__ ull add2(ull a, ull b) {
    ull d; asm("add.rn.f32x2 %0,%1,%2;" : "=l"(d) : "l"(a), "l"(b)); return d;
}

// ---------------- scratch (device globals; no allocations) ----------------
__device__ __half  g_uhat[(size_t)NJ * B_ * NK * NM];       // [j][b][k][m] fp16, 47.2 MB
__device__ float   g_s0part[(size_t)9  * B_ * NJ * NM];     // [kc][pair][m]
__device__ float   g_spart0[(size_t)36 * B_ * NJ * NM];     // route<0> partials
__device__ float   g_spart1[(size_t)36 * B_ * NJ * NM];     // route<1> partials
__device__ float   g_w0[B_ * NJ * NM];                      // v0
__device__ float   g_w1[B_ * NJ * NM];                      // v0 + v1

// =============== Kernel 1: build u_hat (fp16, f32x2 math) + s0 partials ====
__global__ void __launch_bounds__(128) uhat_kernel(const float* __restrict__ x,
                                                   const float* __restrict__ Ws) {
    extern __shared__ float sm[];
    __half2* su = (__half2*)(sm + 8 * 128 * 12);   // [8*128][10] half2 = 40,960 B
    const int kb = blockIdx.x * 128;
    const int j  = blockIdx.y;
    const int b0 = blockIdx.z * 8;
    const int tid = threadIdx.x;

    for (int f = tid; f < 2048; f += 128) {
        int b = f >> 8, r = f & 255;
        int k = r >> 1, q = r & 1;
        float4 v4 = *(const float4*)(x + ((size_t)(b0 + b) * NK + kb + k) * NI + q * 4);
        *(float4*)(sm + (b * 128 + k) * 12 + q * 4) = v4;
    }
    __syncthreads();

    const int p = tid & 31, g = tid >> 5;
    // acc2[b][mp]: f32x2 accumulators, lanes = (m0,m1) / (m2,m3)
    ull acc2[16];
#pragma unroll
    for (int t = 0; t < 16; t++) acc2[t] = 0ull;

    for (int ki = 0; ki < 4; ki++) {
        const int kl = ki * 32 + p;
        const int k  = kb + kl;
        const float4* wp = (const float4*)(Ws + (((size_t)j * NK + k) * NM + g * 4) * NI);
        float4 w[8];
#pragma unroll
        for (int t = 0; t < 8; t++) w[t] = wp[t];
        const float* wf = (const float*)w;             // wf[mi*8+ii]
        // pack weights across m-pairs: wp2[mp*8+ii] = {w[m(2mp)][ii], w[m(2mp+1)][ii]}
        ull wp2[16];
#pragma unroll
        for (int ii = 0; ii < 8; ii++) {
            wp2[ii]     = pk2(wf[ii],      wf[8 + ii]);
            wp2[8 + ii] = pk2(wf[16 + ii], wf[24 + ii]);
        }
#pragma unroll
        for (int b = 0; b < 8; b++) {
            const float* xr = sm + (b * 128 + kl) * 12;
            float4 xa = *(const float4*)xr;
            float4 xb = *(const float4*)(xr + 4);
            const float xs[8] = {xa.x, xa.y, xa.z, xa.w, xb.x, xb.y, xb.z, xb.w};
            ull X[8];
#pragma unroll
            for (int ii = 0; ii < 8; ii++) X[ii] = pk2(xs[ii], xs[ii]);
            ull u0 = mul2(X[0], wp2[0]);
            ull u1 = mul2(X[0], wp2[8]);
#pragma unroll
            for (int ii = 1; ii < 8; ii++) {
                u0 = fma2(X[ii], wp2[ii],     u0);
                u1 = fma2(X[ii], wp2[8 + ii], u1);
            }
            acc2[b * 2]     = add2(acc2[b * 2],     u0);
            acc2[b * 2 + 1] = add2(acc2[b * 2 + 1], u1);
            float l0, h0, l1, h1;
            upk2(u0, l0, h0); upk2(u1, l1, h1);
            su[(b * 128 + kl) * 10 + g * 2]     = __float22half2_rn(make_float2(l0, h0));
            su[(b * 128 + kl) * 10 + g * 2 + 1] = __float22half2_rn(make_float2(l1, h1));
        }
    }
    __syncthreads();

    for (int f = tid; f < 2048; f += 128) {    // 2048 uint4
        int b = f >> 8, r = f & 255;
        int kl = r >> 1, q2 = r & 1;
        const uint2* s2 = (const uint2*)(su + (b * 128 + kl) * 10 + q2 * 4);
        uint4 o; o.x = s2[0].x; o.y = s2[0].y; o.z = s2[1].x; o.w = s2[1].y;
        *(uint4*)(g_uhat + (((size_t)j * B_ + b0 + b) * NK + kb + kl) * NM + q2 * 8) = o;
    }

    float* buf = sm;
#pragma unroll
    for (int b = 0; b < 8; b++) {
        float a0, a1, a2, a3;
        upk2(acc2[b * 2],     a0, a1);
        upk2(acc2[b * 2 + 1], a2, a3);
        buf[p * 129 + b * 16 + g * 4 + 0] = a0;
        buf[p * 129 + b * 16 + g * 4 + 1] = a1;
        buf[p * 129 + b * 16 + g * 4 + 2] = a2;
        buf[p * 129 + b * 16 + g * 4 + 3] = a3;
    }
    __syncthreads();
    if (tid < 128) {
        float s = 0.f;
#pragma unroll
        for (int pp = 0; pp < 32; pp++) s += buf[pp * 129 + tid];
        int bloc = tid >> 4, m = tid & 15;
        g_s0part[(((size_t)blockIdx.x * B_ + (b0 + bloc)) * NJ + j) * NM + m] = s;
    }
}

// =============== Kernel 2: compute routing vector (warp per pair) ==========
template <int ITER>
__global__ void compute_w_kernel() {
    const int warp = (blockIdx.x * blockDim.x + threadIdx.x) >> 5;
    const int lane = threadIdx.x & 31;
    if (warp >= B_ * NJ) return;
    const int q = lane >> 3, t = lane & 7;
    const float* part = (ITER == 0) ? g_s0part : g_spart0;
    const int P = (ITER == 0) ? 9 : 36;
    float4 s = make_float4(0.f, 0.f, 0.f, 0.f);
#pragma unroll
    for (int p = t; p < P; p += 8) {
        float4 u = *(const float4*)(part + ((size_t)p * (B_ * NJ) + warp) * NM + q * 4);
        s.x += u.x; s.y += u.y; s.z += u.z; s.w += u.w;
    }
#pragma unroll
    for (int off = 4; off; off >>= 1) {
        s.x += __shfl_down_sync(0xFFFFFFFFu, s.x, off);
        s.y += __shfl_down_sync(0xFFFFFFFFu, s.y, off);
        s.z += __shfl_down_sync(0xFFFFFFFFu, s.z, off);
        s.w += __shfl_down_sync(0xFFFFFFFFu, s.w, off);
    }
    if (ITER == 0) { s.x *= 0.1f; s.y *= 0.1f; s.z *= 0.1f; s.w *= 0.1f; }
    float n2 = s.x * s.x + s.y * s.y + s.z * s.z + s.w * s.w;
    float n2tot = 0.f;
#pragma unroll
    for (int qq = 0; qq < 4; qq++) n2tot += __shfl_sync(0xFFFFFFFFu, n2, qq * 8);
    const float f = sqrtf(n2tot) / (1.f + n2tot);
    if (t == 0) {
        float4 o = make_float4(s.x * f, s.y * f, s.z * f, s.w * f);
        if (ITER == 1) {
            float4 w0 = *(const float4*)(g_w0 + warp * NM + q * 4);
            o.x += w0.x; o.y += w0.y; o.z += w0.z; o.w += w0.w;
        }
        float* dst = (ITER == 0) ? g_w0 : g_w1;
        *(float4*)(dst + warp * NM + q * 4) = o;
    }
}

// =============== Kernel 3: fused routing pass ==============================
// grid (36, 32), block 320. Phase A now 256 threads (2/pair x 5 j).
template <int ITER>
__global__ void __launch_bounds__(320) route_kernel() {
    extern __shared__ float sm[];
    __half2* uh = (__half2*)sm;            // [128 pairs][UHR half2]
    float* cs = sm + 128 * UHR;            // [128][10]
    float* ws = cs + 1280;                 // [4][160] routing vector
    const int kb = blockIdx.x * 32;
    const int b0 = blockIdx.y * 4;
    const int tid = threadIdx.x;

    // ---- stream the u_hat tile FIRST (front-batched LDG.128)
#pragma unroll
    for (int it = 0; it < 8; it++) {
        int f = it * 320 + tid;            // 0..2559 uint4
        int q2 = f & 1, kl = (f >> 1) & 31, bl = (f >> 6) & 3, j = f >> 8;
        uint4 u = *(const uint4*)(g_uhat + (((size_t)j * B_ + b0 + bl) * NK + kb + kl) * NM + q2 * 8);
        *(uint4*)(uh + (bl * 32 + kl) * UHR + j * 8 + q2 * 4) = u;   // STS.128
    }

    // ---- prologue: broadcast-read precomputed routing vector (640 floats)
    {
        const float* gw = (ITER == 0) ? g_w0 : g_w1;
        for (int f = tid; f < 640; f += 320) ws[f] = gw[b0 * 160 + f];
    }
    __syncthreads();

    // ---- phase A: logits + softmax; 256 threads = (pair, j-half)
    if (tid < 256) {
        const int pair = tid >> 1, jh = tid & 1;
        const int bl = pair >> 5;
        const uint4* row = (const uint4*)(uh + pair * UHR);
        const float* wr = ws + bl * 160;
        float L[5];
#pragma unroll
        for (int jj = 0; jj < 5; jj++) {
            const int j = jh * 5 + jj;
            uint4 a = row[j * 2];
            uint4 b = row[j * 2 + 1];
            const unsigned int ua[8] = {a.x, a.y, a.z, a.w, b.x, b.y, b.z, b.w};
            float d = 0.f;
#pragma unroll
            for (int q = 0; q < 8; q++) {
                float2 f2 = __half22float2(*(const __half2*)&ua[q]);
                d += f2.x * wr[j * 16 + q * 2] + f2.y * wr[j * 16 + q * 2 + 1];
            }
            L[jj] = d;
        }
        float mx = L[0];
#pragma unroll
        for (int jj = 1; jj < 5; jj++) mx = fmaxf(mx, L[jj]);
        mx = fmaxf(mx, __shfl_xor_sync(0xFFFFFFFFu, mx, 1));
        float e[5], ssum = 0.f;
#pragma unroll
        for (int jj = 0; jj < 5; jj++) { e[jj] = __expf(L[jj] - mx); ssum += e[jj]; }
        ssum += __shfl_xor_sync(0xFFFFFFFFu, ssum, 1);
        const float inv = 1.f / ssum;
#pragma unroll
        for (int jj = 0; jj < 5; jj++) cs[pair * 10 + jh * 5 + jj] = e[jj] * inv;
    }
    __syncthreads();

    // ---- phase B: s partials, thread = (bl, j, mh): 4*10*8 = 320
    {
        const int bl = tid / 80, r = tid % 80, j = r >> 3, mh = r & 7;
        float2 acc = make_float2(0.f, 0.f);
        const __half2* uhb = uh + (bl * 32) * UHR + j * 8 + mh;
        const float* csb = cs + (bl * 32) * 10 + j;
#pragma unroll
        for (int kl = 0; kl < 32; kl++) {
            float c = csb[kl * 10];
            float2 f2 = __half22float2(uhb[kl * UHR]);
            acc.x += c * f2.x; acc.y += c * f2.y;
        }
        float* dst = (ITER == 0) ? g_spart0 : g_spart1;
        *(float2*)(dst + ((((size_t)blockIdx.x * B_) + (b0 + bl)) * NJ + j) * NM + mh * 2) = acc;
    }
}

// =============== Kernel 4: final reduce + squash (warp per pair) ===========
__global__ void squash_final(float* __restrict__ out) {
    const int warp = (blockIdx.x * blockDim.x + threadIdx.x) >> 5;
    const int lane = threadIdx.x & 31;
    if (warp >= B_ * NJ) return;
    const int q = lane >> 3, t = lane & 7;
    float4 s = make_float4(0.f, 0.f, 0.f, 0.f);
#pragma unroll
    for (int p = t; p < 36; p += 8) {
        float4 u = *(const float4*)(g_spart1 + ((size_t)p * (B_ * NJ) + warp) * NM + q * 4);
        s.x += u.x; s.y += u.y; s.z += u.z; s.w += u.w;
    }
#pragma unroll
    for (int off = 4; off; off >>= 1) {
        s.x += __shfl_down_sync(0xFFFFFFFFu, s.x, off);
        s.y += __shfl_down_sync(0xFFFFFFFFu, s.y, off);
        s.z += __shfl_down_sync(0xFFFFFFFFu, s.z, off);
        s.w += __shfl_down_sync(0xFFFFFFFFu, s.w, off);
    }
    float n2 = s.x * s.x + s.y * s.y + s.z * s.z + s.w * s.w;
    float n2tot = 0.f;
#pragma unroll
    for (int qq = 0; qq < 4; qq++) n2tot += __shfl_sync(0xFFFFFFFFu, n2, qq * 8);
    const float f = sqrtf(n2tot) / (1.f + n2tot);
    if (t == 0)
        *(float4*)(out + warp * NM + q * 4) = make_float4(s.x * f, s.y * f, s.z * f, s.w * f);
}

// ---------------------------------------------------------------------------
extern "C" void kernel_launch(void* const* d_in, const int* in_sizes, int n_in,
                              void* d_out, int out_size) {
    const float* x  = (const float*)d_in[0];
    const float* Ws = (const float*)d_in[1];
    if (n_in >= 2 && in_sizes[0] == NJ * NK * NM * NI) { const float* t = x; x = Ws; Ws = t; }
    float* out = (float*)d_out;

    const int SMEM_U = 8 * 128 * 12 * 4 + 8 * 128 * 10 * 4;          // 90,112 B
    const int SMEM_R = (128 * UHR + 1280 + 640) * 4;                 // 50,688 B
    cudaFuncSetAttribute(uhat_kernel,     cudaFuncAttributeMaxDynamicSharedMemorySize, SMEM_U);
    cudaFuncSetAttribute(route_kernel<0>, cudaFuncAttributeMaxDynamicSharedMemorySize, SMEM_R);
    cudaFuncSetAttribute(route_kernel<1>, cudaFuncAttributeMaxDynamicSharedMemorySize, SMEM_R);

    uhat_kernel<<<dim3(9, 10, 16), 128, SMEM_U>>>(x, Ws);
    compute_w_kernel<0><<<160, 256>>>();
    route_kernel<0><<<dim3(36, 32), 320, SMEM_R>>>();
    compute_w_kernel<1><<<160, 256>>>();
    route_kernel<1><<<dim3(36, 32), 320, SMEM_R>>>();
    squash_final<<<160, 256>>>(out);
}

// round 10
// speedup vs baseline: 1.0974x; 1.0974x over previous
#include <cuda_runtime.h>
#include <cuda_fp16.h>
#include <math.h>

#define B_   128
#define NJ   10
#define NK   1152
#define NM   16
#define NI   8
#define UHR  84          // route smem row pitch in half2 (80 data + 4 pad)

// ---------------- scratch (device globals; no allocations) ----------------
// u_hat fp16, layout [j][b][g][k][m4] stored as uint2 (one uint2 = 4 half = m-quad)
__device__ uint2   g_uhat[(size_t)NJ * B_ * 4 * NK];        // 47.2 MB
__device__ float   g_s0part[(size_t)9  * B_ * NJ * NM];     // [kc][pair][m]
__device__ float   g_spart0[(size_t)36 * B_ * NJ * NM];
__device__ float   g_spart1[(size_t)36 * B_ * NJ * NM];
__device__ float   g_w1[B_ * NJ * NM];                      // v0 + v1

// =============== Kernel 1: build u_hat (direct coalesced stores) ===========
// grid (9,10,16), block 128, smem 48KB -> 4 CTA/SM.
__global__ void __launch_bounds__(128) uhat_kernel(const float* __restrict__ x,
                                                   const float* __restrict__ Ws) {
    extern __shared__ float sm[];
    const int kb = blockIdx.x * 128;
    const int j  = blockIdx.y;
    const int b0 = blockIdx.z * 8;
    const int tid = threadIdx.x;

    // stage x[b0..b0+7, kb..kb+127, 0:8], padded row = 12 floats
    for (int f = tid; f < 2048; f += 128) {
        int b = f >> 8, r = f & 255;
        int k = r >> 1, q = r & 1;
        float4 v4 = *(const float4*)(x + ((size_t)(b0 + b) * NK + kb + k) * NI + q * 4);
        *(float4*)(sm + (b * 128 + k) * 12 + q * 4) = v4;
    }
    __syncthreads();

    const int p = tid & 31, g = tid >> 5;
    float acc[32];
#pragma unroll
    for (int t = 0; t < 32; t++) acc[t] = 0.f;

    for (int ki = 0; ki < 4; ki++) {
        const int kl = ki * 32 + p;
        const int k  = kb + kl;
        const float4* wp = (const float4*)(Ws + (((size_t)j * NK + k) * NM + g * 4) * NI);
        float4 w[8];
#pragma unroll
        for (int t = 0; t < 8; t++) w[t] = wp[t];
#pragma unroll
        for (int b = 0; b < 8; b++) {
            const float* xr = sm + (b * 128 + kl) * 12;
            float4 xa = *(const float4*)xr;
            float4 xb = *(const float4*)(xr + 4);
            float4 u;
            u.x = w[0].x*xa.x + w[0].y*xa.y + w[0].z*xa.z + w[0].w*xa.w
                + w[1].x*xb.x + w[1].y*xb.y + w[1].z*xb.z + w[1].w*xb.w;
            u.y = w[2].x*xa.x + w[2].y*xa.y + w[2].z*xa.z + w[2].w*xa.w
                + w[3].x*xb.x + w[3].y*xb.y + w[3].z*xb.z + w[3].w*xb.w;
            u.z = w[4].x*xa.x + w[4].y*xa.y + w[4].z*xa.z + w[4].w*xa.w
                + w[5].x*xb.x + w[5].y*xb.y + w[5].z*xb.z + w[5].w*xb.w;
            u.w = w[6].x*xa.x + w[6].y*xa.y + w[6].z*xa.z + w[6].w*xa.w
                + w[7].x*xb.x + w[7].y*xb.y + w[7].z*xb.z + w[7].w*xb.w;
            // direct coalesced store: warp = fixed g, 32 consecutive k -> 256B run
            __half2 h0 = __float22half2_rn(make_float2(u.x, u.y));
            __half2 h1 = __float22half2_rn(make_float2(u.z, u.w));
            uint2 o;
            o.x = reinterpret_cast<unsigned&>(h0);
            o.y = reinterpret_cast<unsigned&>(h1);
            g_uhat[(((size_t)j * B_ + b0 + b) * 4 + g) * NK + k] = o;
            acc[b * 4 + 0] += u.x;
            acc[b * 4 + 1] += u.y;
            acc[b * 4 + 2] += u.z;
            acc[b * 4 + 3] += u.w;
        }
    }
    __syncthreads();   // x region no longer needed

    // in-block k-reduction (fp32) for s0 partials; reuse x region
    float* buf = sm;
#pragma unroll
    for (int b = 0; b < 8; b++)
#pragma unroll
        for (int t = 0; t < 4; t++)
            buf[p * 129 + b * 16 + g * 4 + t] = acc[b * 4 + t];
    __syncthreads();
    if (tid < 128) {
        float s = 0.f;
#pragma unroll
        for (int pp = 0; pp < 32; pp++) s += buf[pp * 129 + tid];
        int bloc = tid >> 4, m = tid & 15;
        g_s0part[(((size_t)blockIdx.x * B_ + (b0 + bloc)) * NJ + j) * NM + m] = s;
    }
}

// =============== Kernel 2: fused routing pass ==============================
// ITER 0: w = v0 computed inline from g_s0part (9 partials, overlapped w/ loads)
// ITER 1: w = g_w1 (precomputed v0+v1)
// grid (36, 32), block 320. Tile 4b x 32k x 10j x 16m.
template <int ITER>
__global__ void __launch_bounds__(320) route_kernel() {
    extern __shared__ float sm[];
    __half2* uh = (__half2*)sm;            // [128 pairs][UHR half2]
    float* cs = sm + 128 * UHR;            // [128][10]
    float* ws = cs + 1280;                 // [4][160] routing vector
    const int kb = blockIdx.x * 32;
    const int b0 = blockIdx.y * 4;
    const int tid = threadIdx.x;

    // ---- stream the u_hat tile FIRST (front-batched LDG.128, 256B runs)
#pragma unroll
    for (int it = 0; it < 8; it++) {
        int f = it * 320 + tid;            // 0..2559 uint4
        int kp = f & 15, g = (f >> 4) & 3, bl = (f >> 6) & 3, j = f >> 8;
        uint4 u = *(const uint4*)(g_uhat + ((((size_t)j * B_ + b0 + bl) * 4 + g) * NK + kb + kp * 2));
        const int row = bl * 32 + kp * 2;
        *(uint2*)(uh + row * UHR + j * 8 + g * 2)       = make_uint2(u.x, u.y);
        *(uint2*)(uh + (row + 1) * UHR + j * 8 + g * 2) = make_uint2(u.z, u.w);
    }

    // ---- prologue: routing vector (overlaps with tile-load drain)
    if (ITER == 0) {
        for (int pv = tid; pv < 640; pv += 320) {
            const int bl = pv / 160, r = pv % 160;      // j = r>>4, m = r&15
            const size_t base = (((size_t)(b0 + bl) * NJ + (r >> 4)) * NM) + (r & 15);
            const size_t stride = (size_t)B_ * NJ * NM;
            float s0 = 0.f;
#pragma unroll
            for (int pp = 0; pp < 9; pp++) s0 += g_s0part[base + pp * stride];
            s0 *= 0.1f;
            float n2 = s0 * s0;
            n2 += __shfl_xor_sync(0xFFFFFFFFu, n2, 1);
            n2 += __shfl_xor_sync(0xFFFFFFFFu, n2, 2);
            n2 += __shfl_xor_sync(0xFFFFFFFFu, n2, 4);
            n2 += __shfl_xor_sync(0xFFFFFFFFu, n2, 8);
            ws[pv] = s0 * (sqrtf(n2) / (1.f + n2));
        }
    } else {
        for (int f = tid; f < 640; f += 320) ws[f] = g_w1[b0 * 160 + f];
    }
    __syncthreads();

    // ---- phase A: logits + softmax, one thread per (b,k); LDS.128 reads
    if (tid < 128) {
        const int bl = tid >> 5;
        const uint4* row = (const uint4*)(uh + tid * UHR);
        const float* wr = ws + bl * 160;
        float L[10];
#pragma unroll
        for (int j = 0; j < 10; j++) {
            uint4 a = row[j * 2];
            uint4 b = row[j * 2 + 1];
            const unsigned int ua[8] = {a.x, a.y, a.z, a.w, b.x, b.y, b.z, b.w};
            float d = 0.f;
#pragma unroll
            for (int q = 0; q < 8; q++) {
                float2 f2 = __half22float2(*(const __half2*)&ua[q]);
                d += f2.x * wr[j * 16 + q * 2] + f2.y * wr[j * 16 + q * 2 + 1];
            }
            L[j] = d;
        }
        float mx = L[0];
#pragma unroll
        for (int j = 1; j < 10; j++) mx = fmaxf(mx, L[j]);
        float e[10], ssum = 0.f;
#pragma unroll
        for (int j = 0; j < 10; j++) { e[j] = __expf(L[j] - mx); ssum += e[j]; }
        const float inv = 1.f / ssum;
#pragma unroll
        for (int j = 0; j < 10; j++) cs[tid * 10 + j] = e[j] * inv;
    }
    __syncthreads();

    // ---- phase B: s partials, thread = (bl, j, mh): 4*10*8 = 320
    {
        const int bl = tid / 80, r = tid % 80, j = r >> 3, mh = r & 7;
        float2 acc = make_float2(0.f, 0.f);
        const __half2* uhb = uh + (bl * 32) * UHR + j * 8 + mh;
        const float* csb = cs + (bl * 32) * 10 + j;
#pragma unroll
        for (int kl = 0; kl < 32; kl++) {
            float c = csb[kl * 10];
            float2 f2 = __half22float2(uhb[kl * UHR]);
            acc.x += c * f2.x; acc.y += c * f2.y;
        }
        float* dst = (ITER == 0) ? g_spart0 : g_spart1;
        *(float2*)(dst + ((((size_t)blockIdx.x * B_) + (b0 + bl)) * NJ + j) * NM + mh * 2) = acc;
    }
}

// =============== Kernel 3: w1 = v0 + v1 (warp per pair) ====================
__global__ void compute_w1_kernel() {
    const int warp = (blockIdx.x * blockDim.x + threadIdx.x) >> 5;
    const int lane = threadIdx.x & 31;
    if (warp >= B_ * NJ) return;
    const int q = lane >> 3, t = lane & 7;
    float4 s0 = make_float4(0.f, 0.f, 0.f, 0.f);
    float4 s1 = make_float4(0.f, 0.f, 0.f, 0.f);
#pragma unroll
    for (int p = t; p < 9; p += 8) {
        float4 u = *(const float4*)(g_s0part + ((size_t)p * (B_ * NJ) + warp) * NM + q * 4);
        s0.x += u.x; s0.y += u.y; s0.z += u.z; s0.w += u.w;
    }
#pragma unroll
    for (int p = t; p < 36; p += 8) {
        float4 u = *(const float4*)(g_spart0 + ((size_t)p * (B_ * NJ) + warp) * NM + q * 4);
        s1.x += u.x; s1.y += u.y; s1.z += u.z; s1.w += u.w;
    }
#pragma unroll
    for (int off = 4; off; off >>= 1) {
        s0.x += __shfl_down_sync(0xFFFFFFFFu, s0.x, off);
        s0.y += __shfl_down_sync(0xFFFFFFFFu, s0.y, off);
        s0.z += __shfl_down_sync(0xFFFFFFFFu, s0.z, off);
        s0.w += __shfl_down_sync(0xFFFFFFFFu, s0.w, off);
        s1.x += __shfl_down_sync(0xFFFFFFFFu, s1.x, off);
        s1.y += __shfl_down_sync(0xFFFFFFFFu, s1.y, off);
        s1.z += __shfl_down_sync(0xFFFFFFFFu, s1.z, off);
        s1.w += __shfl_down_sync(0xFFFFFFFFu, s1.w, off);
    }
    s0.x *= 0.1f; s0.y *= 0.1f; s0.z *= 0.1f; s0.w *= 0.1f;
    float a2 = s0.x * s0.x + s0.y * s0.y + s0.z * s0.z + s0.w * s0.w;   // on t==0
    float b2 = s1.x * s1.x + s1.y * s1.y + s1.z * s1.z + s1.w * s1.w;
    float a2t = 0.f, b2t = 0.f;
#pragma unroll
    for (int qq = 0; qq < 4; qq++) {
        a2t += __shfl_sync(0xFFFFFFFFu, a2, qq * 8);
        b2t += __shfl_sync(0xFFFFFFFFu, b2, qq * 8);
    }
    const float fa = sqrtf(a2t) / (1.f + a2t);
    const float fb = sqrtf(b2t) / (1.f + b2t);
    if (t == 0) {
        float4 o = make_float4(s0.x * fa + s1.x * fb, s0.y * fa + s1.y * fb,
                               s0.z * fa + s1.z * fb, s0.w * fa + s1.w * fb);
        *(float4*)(g_w1 + warp * NM + q * 4) = o;
    }
}

// =============== Kernel 4: final reduce + squash (warp per pair) ===========
__global__ void squash_final(float* __restrict__ out) {
    const int warp = (blockIdx.x * blockDim.x + threadIdx.x) >> 5;
    const int lane = threadIdx.x & 31;
    if (warp >= B_ * NJ) return;
    const int q = lane >> 3, t = lane & 7;
    float4 s = make_float4(0.f, 0.f, 0.f, 0.f);
#pragma unroll
    for (int p = t; p < 36; p += 8) {
        float4 u = *(const float4*)(g_spart1 + ((size_t)p * (B_ * NJ) + warp) * NM + q * 4);
        s.x += u.x; s.y += u.y; s.z += u.z; s.w += u.w;
    }
#pragma unroll
    for (int off = 4; off; off >>= 1) {
        s.x += __shfl_down_sync(0xFFFFFFFFu, s.x, off);
        s.y += __shfl_down_sync(0xFFFFFFFFu, s.y, off);
        s.z += __shfl_down_sync(0xFFFFFFFFu, s.z, off);
        s.w += __shfl_down_sync(0xFFFFFFFFu, s.w, off);
    }
    float n2 = s.x * s.x + s.y * s.y + s.z * s.z + s.w * s.w;
    float n2tot = 0.f;
#pragma unroll
    for (int qq = 0; qq < 4; qq++) n2tot += __shfl_sync(0xFFFFFFFFu, n2, qq * 8);
    const float f = sqrtf(n2tot) / (1.f + n2tot);
    if (t == 0)
        *(float4*)(out + warp * NM + q * 4) = make_float4(s.x * f, s.y * f, s.z * f, s.w * f);
}

// ---------------------------------------------------------------------------
extern "C" void kernel_launch(void* const* d_in, const int* in_sizes, int n_in,
                              void* d_out, int out_size) {
    const float* x  = (const float*)d_in[0];
    const float* Ws = (const float*)d_in[1];
    if (n_in >= 2 && in_sizes[0] == NJ * NK * NM * NI) { const float* t = x; x = Ws; Ws = t; }
    float* out = (float*)d_out;

    const int SMEM_U = 8 * 128 * 12 * 4;                             // 49,152 B
    const int SMEM_R = (128 * UHR + 1280 + 640) * 4;                 // 50,688 B
    cudaFuncSetAttribute(uhat_kernel,     cudaFuncAttributeMaxDynamicSharedMemorySize, SMEM_U);
    cudaFuncSetAttribute(route_kernel<0>, cudaFuncAttributeMaxDynamicSharedMemorySize, SMEM_R);
    cudaFuncSetAttribute(route_kernel<1>, cudaFuncAttributeMaxDynamicSharedMemorySize, SMEM_R);

    // 1) u_hat (fp16, [j][b][g][k][m4], direct stores) + s0 partials
    uhat_kernel<<<dim3(9, 10, 16), 128, SMEM_U>>>(x, Ws);
    // 2) iter0: v0 inline, c=softmax(u.v0), s1 partials
    route_kernel<0><<<dim3(36, 32), 320, SMEM_R>>>();
    // 3) w1 = v0 + v1
    compute_w1_kernel<<<160, 256>>>();
    // 4) iter1: c=softmax(u.w1), s2 partials
    route_kernel<1><<<dim3(36, 32), 320, SMEM_R>>>();
    // 5) v2 = squash(s2) -> d_out
    squash_final<<<160, 256>>>(out);
}

// round 11
// speedup vs baseline: 1.2102x; 1.1028x over previous
#include <cuda_runtime.h>
#include <cuda_fp16.h>
#include <math.h>

#define B_   128
#define NJ   10
#define NK   1152
#define NM   16
#define NI   8
#define UHR  84          // route smem row pitch in half2 (80 data + 4 pad)
#define BT   16          // b per uhat block

// ---------------- scratch (device globals; no allocations) ----------------
// u_hat fp16, layout [j][b][g][k][m4] stored as uint2 (one uint2 = 4 half = m-quad)
__device__ uint2   g_uhat[(size_t)NJ * B_ * 4 * NK];        // 47.2 MB
__device__ float   g_s0part[(size_t)9  * B_ * NJ * NM];     // [kc][pair][m]
__device__ float   g_spart0[(size_t)36 * B_ * NJ * NM];
__device__ float   g_spart1[(size_t)36 * B_ * NJ * NM];
__device__ float   g_w1[B_ * NJ * NM];                      // v0 + v1

// =============== Kernel 1: build u_hat, 16-b tile (halved Ws traffic) ======
// grid (9,10,8), block 128, smem 96KB.
__global__ void __launch_bounds__(128) uhat_kernel(const float* __restrict__ x,
                                                   const float* __restrict__ Ws) {
    extern __shared__ float sm[];
    const int kb = blockIdx.x * 128;
    const int j  = blockIdx.y;
    const int b0 = blockIdx.z * BT;
    const int tid = threadIdx.x;

    // stage x[b0..b0+15, kb..kb+127, 0:8], padded row = 12 floats
    for (int f = tid; f < 4096; f += 128) {
        int b = f >> 8, r = f & 255;
        int k = r >> 1, q = r & 1;
        float4 v4 = *(const float4*)(x + ((size_t)(b0 + b) * NK + kb + k) * NI + q * 4);
        *(float4*)(sm + (b * 128 + k) * 12 + q * 4) = v4;
    }
    __syncthreads();

    const int p = tid & 31, g = tid >> 5;
    float acc[BT * 4];
#pragma unroll
    for (int t = 0; t < BT * 4; t++) acc[t] = 0.f;

    for (int ki = 0; ki < 4; ki++) {
        const int kl = ki * 32 + p;
        const int k  = kb + kl;
        const float4* wp = (const float4*)(Ws + (((size_t)j * NK + k) * NM + g * 4) * NI);
        float4 w[8];
#pragma unroll
        for (int t = 0; t < 8; t++) w[t] = wp[t];
#pragma unroll
        for (int b = 0; b < BT; b++) {
            const float* xr = sm + (b * 128 + kl) * 12;
            float4 xa = *(const float4*)xr;
            float4 xb = *(const float4*)(xr + 4);
            float4 u;
            u.x = w[0].x*xa.x + w[0].y*xa.y + w[0].z*xa.z + w[0].w*xa.w
                + w[1].x*xb.x + w[1].y*xb.y + w[1].z*xb.z + w[1].w*xb.w;
            u.y = w[2].x*xa.x + w[2].y*xa.y + w[2].z*xa.z + w[2].w*xa.w
                + w[3].x*xb.x + w[3].y*xb.y + w[3].z*xb.z + w[3].w*xb.w;
            u.z = w[4].x*xa.x + w[4].y*xa.y + w[4].z*xa.z + w[4].w*xa.w
                + w[5].x*xb.x + w[5].y*xb.y + w[5].z*xb.z + w[5].w*xb.w;
            u.w = w[6].x*xa.x + w[6].y*xa.y + w[6].z*xa.z + w[6].w*xa.w
                + w[7].x*xb.x + w[7].y*xb.y + w[7].z*xb.z + w[7].w*xb.w;
            __half2 h0 = __float22half2_rn(make_float2(u.x, u.y));
            __half2 h1 = __float22half2_rn(make_float2(u.z, u.w));
            uint2 o;
            o.x = reinterpret_cast<unsigned&>(h0);
            o.y = reinterpret_cast<unsigned&>(h1);
            g_uhat[(((size_t)j * B_ + b0 + b) * 4 + g) * NK + k] = o;   // 256B run/warp
            acc[b * 4 + 0] += u.x;
            acc[b * 4 + 1] += u.y;
            acc[b * 4 + 2] += u.z;
            acc[b * 4 + 3] += u.w;
        }
    }
    __syncthreads();   // x region no longer needed

    // in-block k-reduction (fp32) for s0 partials; reuse x region
    float* buf = sm;   // [32 p][257] (256 (b,m) + pad)
#pragma unroll
    for (int b = 0; b < BT; b++)
#pragma unroll
        for (int t = 0; t < 4; t++)
            buf[p * 257 + b * 16 + g * 4 + t] = acc[b * 4 + t];
    __syncthreads();
#pragma unroll
    for (int it = 0; it < 2; it++) {
        const int idx = it * 128 + tid;      // 256 (b,m) items
        float s = 0.f;
#pragma unroll
        for (int pp = 0; pp < 32; pp++) s += buf[pp * 257 + idx];
        const int bloc = idx >> 4, m = idx & 15;
        g_s0part[(((size_t)blockIdx.x * B_ + (b0 + bloc)) * NJ + j) * NM + m] = s;
    }
}

// =============== Kernel 2: fused routing pass ==============================
// ITER 0: w = v0 computed inline from g_s0part; ITER 1: w = g_w1.
// grid (36, 32), block 320. Tile 4b x 32k x 10j x 16m.
template <int ITER>
__global__ void __launch_bounds__(320) route_kernel() {
    extern __shared__ float sm[];
    __half2* uh = (__half2*)sm;            // [128 pairs][UHR half2]
    float* cs = sm + 128 * UHR;            // [128][10]
    float* ws = cs + 1280;                 // [4][160] routing vector
    const int kb = blockIdx.x * 32;
    const int b0 = blockIdx.y * 4;
    const int tid = threadIdx.x;

    // ---- stream the u_hat tile FIRST (front-batched LDG.128, 256B runs)
#pragma unroll
    for (int it = 0; it < 8; it++) {
        int f = it * 320 + tid;            // 0..2559 uint4
        int kp = f & 15, g = (f >> 4) & 3, bl = (f >> 6) & 3, j = f >> 8;
        uint4 u = *(const uint4*)(g_uhat + ((((size_t)j * B_ + b0 + bl) * 4 + g) * NK + kb + kp * 2));
        const int row = bl * 32 + kp * 2;
        *(uint2*)(uh + row * UHR + j * 8 + g * 2)       = make_uint2(u.x, u.y);
        *(uint2*)(uh + (row + 1) * UHR + j * 8 + g * 2) = make_uint2(u.z, u.w);
    }

    // ---- prologue: routing vector (overlaps with tile-load drain)
    if (ITER == 0) {
        for (int pv = tid; pv < 640; pv += 320) {
            const int bl = pv / 160, r = pv % 160;
            const size_t base = (((size_t)(b0 + bl) * NJ + (r >> 4)) * NM) + (r & 15);
            const size_t stride = (size_t)B_ * NJ * NM;
            float s0 = 0.f;
#pragma unroll
            for (int pp = 0; pp < 9; pp++) s0 += g_s0part[base + pp * stride];
            s0 *= 0.1f;
            float n2 = s0 * s0;
            n2 += __shfl_xor_sync(0xFFFFFFFFu, n2, 1);
            n2 += __shfl_xor_sync(0xFFFFFFFFu, n2, 2);
            n2 += __shfl_xor_sync(0xFFFFFFFFu, n2, 4);
            n2 += __shfl_xor_sync(0xFFFFFFFFu, n2, 8);
            ws[pv] = s0 * (sqrtf(n2) / (1.f + n2));
        }
    } else {
        for (int f = tid; f < 640; f += 320) ws[f] = g_w1[b0 * 160 + f];
    }
    __syncthreads();

    // ---- phase A: logits + softmax, one thread per (b,k); LDS.128 reads
    if (tid < 128) {
        const int bl = tid >> 5;
        const uint4* row = (const uint4*)(uh + tid * UHR);
        const float* wr = ws + bl * 160;
        float L[10];
#pragma unroll
        for (int j = 0; j < 10; j++) {
            uint4 a = row[j * 2];
            uint4 b = row[j * 2 + 1];
            const unsigned int ua[8] = {a.x, a.y, a.z, a.w, b.x, b.y, b.z, b.w};
            float d = 0.f;
#pragma unroll
            for (int q = 0; q < 8; q++) {
                float2 f2 = __half22float2(*(const __half2*)&ua[q]);
                d += f2.x * wr[j * 16 + q * 2] + f2.y * wr[j * 16 + q * 2 + 1];
            }
            L[j] = d;
        }
        float mx = L[0];
#pragma unroll
        for (int j = 1; j < 10; j++) mx = fmaxf(mx, L[j]);
        float e[10], ssum = 0.f;
#pragma unroll
        for (int j = 0; j < 10; j++) { e[j] = __expf(L[j] - mx); ssum += e[j]; }
        const float inv = 1.f / ssum;
#pragma unroll
        for (int j = 0; j < 10; j++) cs[tid * 10 + j] = e[j] * inv;
    }
    __syncthreads();

    // ---- phase B: s partials, thread = (bl, j, mh): 4*10*8 = 320
    {
        const int bl = tid / 80, r = tid % 80, j = r >> 3, mh = r & 7;
        float2 acc = make_float2(0.f, 0.f);
        const __half2* uhb = uh + (bl * 32) * UHR + j * 8 + mh;
        const float* csb = cs + (bl * 32) * 10 + j;
#pragma unroll
        for (int kl = 0; kl < 32; kl++) {
            float c = csb[kl * 10];
            float2 f2 = __half22float2(uhb[kl * UHR]);
            acc.x += c * f2.x; acc.y += c * f2.y;
        }
        float* dst = (ITER == 0) ? g_spart0 : g_spart1;
        *(float2*)(dst + ((((size_t)blockIdx.x * B_) + (b0 + bl)) * NJ + j) * NM + mh * 2) = acc;
    }
}

// =============== Kernel 3: w1 = v0 + v1 (warp per pair) ====================
__global__ void compute_w1_kernel() {
    const int warp = (blockIdx.x * blockDim.x + threadIdx.x) >> 5;
    const int lane = threadIdx.x & 31;
    if (warp >= B_ * NJ) return;
    const int q = lane >> 3, t = lane & 7;
    float4 s0 = make_float4(0.f, 0.f, 0.f, 0.f);
    float4 s1 = make_float4(0.f, 0.f, 0.f, 0.f);
#pragma unroll
    for (int p = t; p < 9; p += 8) {
        float4 u = *(const float4*)(g_s0part + ((size_t)p * (B_ * NJ) + warp) * NM + q * 4);
        s0.x += u.x; s0.y += u.y; s0.z += u.z; s0.w += u.w;
    }
#pragma unroll
    for (int p = t; p < 36; p += 8) {
        float4 u = *(const float4*)(g_spart0 + ((size_t)p * (B_ * NJ) + warp) * NM + q * 4);
        s1.x += u.x; s1.y += u.y; s1.z += u.z; s1.w += u.w;
    }
#pragma unroll
    for (int off = 4; off; off >>= 1) {
        s0.x += __shfl_down_sync(0xFFFFFFFFu, s0.x, off);
        s0.y += __shfl_down_sync(0xFFFFFFFFu, s0.y, off);
        s0.z += __shfl_down_sync(0xFFFFFFFFu, s0.z, off);
        s0.w += __shfl_down_sync(0xFFFFFFFFu, s0.w, off);
        s1.x += __shfl_down_sync(0xFFFFFFFFu, s1.x, off);
        s1.y += __shfl_down_sync(0xFFFFFFFFu, s1.y, off);
        s1.z += __shfl_down_sync(0xFFFFFFFFu, s1.z, off);
        s1.w += __shfl_down_sync(0xFFFFFFFFu, s1.w, off);
    }
    s0.x *= 0.1f; s0.y *= 0.1f; s0.z *= 0.1f; s0.w *= 0.1f;
    float a2 = s0.x * s0.x + s0.y * s0.y + s0.z * s0.z + s0.w * s0.w;
    float b2 = s1.x * s1.x + s1.y * s1.y + s1.z * s1.z + s1.w * s1.w;
    float a2t = 0.f, b2t = 0.f;
#pragma unroll
    for (int qq = 0; qq < 4; qq++) {
        a2t += __shfl_sync(0xFFFFFFFFu, a2, qq * 8);
        b2t += __shfl_sync(0xFFFFFFFFu, b2, qq * 8);
    }
    const float fa = sqrtf(a2t) / (1.f + a2t);
    const float fb = sqrtf(b2t) / (1.f + b2t);
    if (t == 0) {
        float4 o = make_float4(s0.x * fa + s1.x * fb, s0.y * fa + s1.y * fb,
                               s0.z * fa + s1.z * fb, s0.w * fa + s1.w * fb);
        *(float4*)(g_w1 + warp * NM + q * 4) = o;
    }
}

// =============== Kernel 4: final reduce + squash (warp per pair) ===========
__global__ void squash_final(float* __restrict__ out) {
    const int warp = (blockIdx.x * blockDim.x + threadIdx.x) >> 5;
    const int lane = threadIdx.x & 31;
    if (warp >= B_ * NJ) return;
    const int q = lane >> 3, t = lane & 7;
    float4 s = make_float4(0.f, 0.f, 0.f, 0.f);
#pragma unroll
    for (int p = t; p < 36; p += 8) {
        float4 u = *(const float4*)(g_spart1 + ((size_t)p * (B_ * NJ) + warp) * NM + q * 4);
        s.x += u.x; s.y += u.y; s.z += u.z; s.w += u.w;
    }
#pragma unroll
    for (int off = 4; off; off >>= 1) {
        s.x += __shfl_down_sync(0xFFFFFFFFu, s.x, off);
        s.y += __shfl_down_sync(0xFFFFFFFFu, s.y, off);
        s.z += __shfl_down_sync(0xFFFFFFFFu, s.z, off);
        s.w += __shfl_down_sync(0xFFFFFFFFu, s.w, off);
    }
    float n2 = s.x * s.x + s.y * s.y + s.z * s.z + s.w * s.w;
    float n2tot = 0.f;
#pragma unroll
    for (int qq = 0; qq < 4; qq++) n2tot += __shfl_sync(0xFFFFFFFFu, n2, qq * 8);
    const float f = sqrtf(n2tot) / (1.f + n2tot);
    if (t == 0)
        *(float4*)(out + warp * NM + q * 4) = make_float4(s.x * f, s.y * f, s.z * f, s.w * f);
}

// ---------------------------------------------------------------------------
extern "C" void kernel_launch(void* const* d_in, const int* in_sizes, int n_in,
                              void* d_out, int out_size) {
    const float* x  = (const float*)d_in[0];
    const float* Ws = (const float*)d_in[1];
    if (n_in >= 2 && in_sizes[0] == NJ * NK * NM * NI) { const float* t = x; x = Ws; Ws = t; }
    float* out = (float*)d_out;

    const int SMEM_U = BT * 128 * 12 * 4;                            // 98,304 B
    const int SMEM_R = (128 * UHR + 1280 + 640) * 4;                 // 50,688 B
    cudaFuncSetAttribute(uhat_kernel,     cudaFuncAttributeMaxDynamicSharedMemorySize, SMEM_U);
    cudaFuncSetAttribute(route_kernel<0>, cudaFuncAttributeMaxDynamicSharedMemorySize, SMEM_R);
    cudaFuncSetAttribute(route_kernel<1>, cudaFuncAttributeMaxDynamicSharedMemorySize, SMEM_R);

    // 1) u_hat (fp16, [j][b][g][k][m4], direct stores, 16-b tile) + s0 partials
    uhat_kernel<<<dim3(9, 10, 8), 128, SMEM_U>>>(x, Ws);
    // 2) iter0: v0 inline, c=softmax(u.v0), s1 partials
    route_kernel<0><<<dim3(36, 32), 320, SMEM_R>>>();
    // 3) w1 = v0 + v1
    compute_w1_kernel<<<160, 256>>>();
    // 4) iter1: c=softmax(u.w1), s2 partials
    route_kernel<1><<<dim3(36, 32), 320, SMEM_R>>>();
    // 5) v2 = squash(s2) -> d_out
    squash_final<<<160, 256>>>(out);
}